// round 7
// baseline (speedup 1.0000x reference)
#include <cuda_runtime.h>
#include <cuda_bf16.h>
#include <cstdint>

#define THT 32
#define TWT 32
#define PH  (THT + 4)
#define PW  (TWT + 4)
#define TPE (PH * PW)     // 1296 elements per staged plane
#define NCH (TPE / 4)     // 324 float4 chunks per plane
#define HH  512
#define WW  1024
#define CC  16
#define NTY 16
#define NTX 32
#define NBK (4 * NTY * NTX)

__device__ float        g_partials[NBK];
__device__ unsigned int g_count = 0;

__host__ __device__ constexpr uint32_t pk(int a, int b, int c, int d) {
    return (uint32_t)(a & 0xFF) | ((uint32_t)(b & 0xFF) << 8) |
           ((uint32_t)(c & 0xFF) << 16) | ((uint32_t)(d & 0xFF) << 24);
}

// Negated composed-sobel weights (bytes = cols dj=-2..1 of the 5x5 kernels).
// gxx*64 = vv(row) x hh(col); gyy*64 = hh(row) x vv(col); gxy*64 = dd(row) x dd(col)
// vv=[1,4,6,4,1] hh=[1,0,-2,0,1] dd=[-1,-2,0,2,1]. Negated because vcmpeq4
// yields 0xFF (= -1 as s8) per match, so dp4a(match, -W) accumulates +W.
#define NXX0 ((int)pk(-1, 0,  2, 0))
#define NXX1 ((int)pk(-4, 0,  8, 0))
#define NXX2 ((int)pk(-6, 0, 12, 0))
#define NXXC ((int)pk(-1,-4, -6,-4))
#define NYY2 ((int)pk( 2, 8, 12, 8))
#define NXY0 ((int)pk(-1,-2,  0, 2))
#define NXY1 ((int)pk(-2,-4,  0, 4))
#define NXY3 ((int)pk( 2, 4,  0,-4))
#define NXY4 ((int)pk( 1, 2,  0,-2))

__device__ __forceinline__ float bf_raw_to_f32(unsigned int u) {
    return __uint_as_float(u << 16);
}

__global__ void __launch_bounds__(256, 5)
steal_nms_kernel(const float* __restrict__ pred, const int* __restrict__ lab,
                 float* __restrict__ out)
{
    __shared__ __nv_bfloat16               sE[CC * TPE];  // exp(pred), bf16
    __shared__ __align__(16) unsigned char sL[TPE];       // label bytes
    __shared__ int4                        sLut[3];       // tap byte-offsets per dir
    __shared__ float                       wsum[8];
    __shared__ double                      sd[256];
    __shared__ unsigned int                s_flag;

    const int tid = threadIdx.x;
    const int b  = blockIdx.z;
    const int h0 = 2 + (int)blockIdx.y * THT;
    const int w0 = 2 + (int)blockIdx.x * TWT;

    if (tid < 3) {
        int4 v;
        if (tid == 0)      v = make_int4(-4, -2, 0, 2);                          // H
        else if (tid == 1) v = make_int4(2 - 4*PW, -2*PW, -2, 2*PW - 4);         // Diag
        else               v = make_int4(-4*PW, -2*PW, 0, 2*PW);                 // V
        sLut[tid] = v;
    }

    // ---- vectorized staging: 324 float4/int4 chunks per plane, 16B-aligned ----
    #pragma unroll
    for (int half = 0; half < 2; ++half) {
        int j = tid + half * 256;
        if (j >= NCH) break;
        int row = j / 9;                   // 0..35
        int c4  = j - row * 9;             // 0..8
        int gh = h0 - 2 + row; if (gh > HH - 1) gh = HH - 1;
        int gw = w0 - 2 + c4 * 4; if (gw > WW - 4) gw = WW - 4;  // clamped lanes unused by valid pixels
        const size_t goff = (size_t)gh * WW + gw;
        const int jj = row * PW + c4 * 4;

        // labels: int4 -> 4 packed bytes
        int4 L = *(const int4*)(lab + (size_t)b * (HH * WW) + goff);
        uint32_t pkl = (uint32_t)(L.x & 0xFF) | ((uint32_t)(L.y & 0xFF) << 8) |
                       ((uint32_t)(L.z & 0xFF) << 16) | ((uint32_t)L.w << 24);
        *(uint32_t*)(sL + jj) = pkl;

        // exp planes: LDG.128 + 4 exp + 2 bf16x2 cvt + STS.64 per class
        const float* p = pred + (size_t)b * CC * (HH * WW) + goff;
        __nv_bfloat16* se = sE + jj;
        #pragma unroll 4
        for (int c = 0; c < CC; ++c) {
            float4 v = *(const float4*)p;
            __nv_bfloat162 lo = __floats2bfloat162_rn(__expf(v.x), __expf(v.y));
            __nv_bfloat162 hi = __floats2bfloat162_rn(__expf(v.z), __expf(v.w));
            uint2 st;
            st.x = *(unsigned int*)&lo;
            st.y = *(unsigned int*)&hi;
            *(uint2*)se = st;
            p  += (size_t)(HH * WW);
            se += TPE;
        }
    }
    __syncthreads();

    float acc = 0.0f;

    #pragma unroll
    for (int p2 = 0; p2 < 4; ++p2) {
        int pid = tid + p2 * 256;
        int lyy = pid >> 5, lxx = pid & 31;
        int h = h0 + lyy, w = w0 + lxx;
        if (h >= HH - 2 || w >= WW - 2) continue;   // interior only

        // ---- 5x5 label window: 5 row-words (cols -2..1), col4-word, corner
        uint32_t A0, A1, A2, A3, A4, Cw, corner;
        {
            int off0 = lyy * PW + lxx;
            uint32_t Ar[5], kb[5];
            #pragma unroll
            for (int r = 0; r < 5; ++r) {
                int off = off0 + r * PW;
                int a = off & ~3, m = off & 3;
                uint32_t u0 = *(const uint32_t*)(sL + a);
                uint32_t u1 = *(const uint32_t*)(sL + a + 4);
                Ar[r] = __byte_perm(u0, u1, 0x3210u + (uint32_t)m * 0x1111u);
                kb[r] = (u1 >> (m * 8)) & 0xFFu;
            }
            A0 = Ar[0]; A1 = Ar[1]; A2 = Ar[2]; A3 = Ar[3]; A4 = Ar[4];
            Cw = kb[0] | (kb[1] << 8) | (kb[2] << 16) | (kb[3] << 24);
            corner = kb[4];
        }

        const char* Ebase = (const char*)sE + 2 * ((lyy + 2) * PW + (lxx + 2));

        #pragma unroll 4
        for (int c = 0; c < CC; ++c, Ebase += 2 * TPE) {
            uint32_t cm = (uint32_t)c * 0x01010101u;
            int e0 = (int)__vcmpeq4(A0, cm);
            int e1 = (int)__vcmpeq4(A1, cm);
            int e2 = (int)__vcmpeq4(A2, cm);
            int e3 = (int)__vcmpeq4(A3, cm);
            int e4 = (int)__vcmpeq4(A4, cm);
            int eC = (int)__vcmpeq4(Cw, cm);
            int mk = (corner == (uint32_t)c) ? 1 : 0;   // corner weight +1 in all three kernels

            int gxx = mk, gyy = mk, gxy = mk;
            gxx = __dp4a(e0, NXX0, gxx);
            gxx = __dp4a(e1, NXX1, gxx);
            gxx = __dp4a(e2, NXX2, gxx);
            gxx = __dp4a(e3, NXX1, gxx);
            gxx = __dp4a(e4, NXX0, gxx);
            gxx = __dp4a(eC, NXXC, gxx);

            gyy = __dp4a(e0, NXXC, gyy);
            gyy = __dp4a(e2, NYY2, gyy);
            gyy = __dp4a(e4, NXXC, gyy);
            gyy = __dp4a(eC, NXX0, gyy);

            gxy = __dp4a(e0, NXY0, gxy);
            gxy = __dp4a(e1, NXY1, gxy);
            gxy = __dp4a(e3, NXY3, gxy);
            gxy = __dp4a(e4, NXY4, gxy);
            gxy = __dp4a(eC, NXY4, gxy);

            // classifier: t = s*gyy/(gxx+64eps), s = sign(-gxy+eps)
            // dir = b2 + (tpos & b1);  b1 = |t|>=tan(pi/10), b2 = |t|>=tan(3pi/10)
            int ai  = (gxy <= 0) ? gyy : -gyy;
            int ua  = abs(ai);
            int ub  = abs(gxx);
            int lhs = ua << 16;
            int nz  = (ai != 0);
            int b1  = (lhs >= 21294 * ub) & nz;           // tan(pi/10)*2^16
            int b2  = (lhs >= 90203 * ub) & nz;           // tan(3pi/10)*2^16
            int tp  = ((ai ^ gxx) >= 0);                  // sign(ai)==sign(gxx)
            int dir = b2 + (tp & b1);                     // 0=H, 1=Diag, 2=V

            int4 o = sLut[dir];
            unsigned int un = *(const unsigned short*)(Ebase);
            unsigned int u0 = *(const unsigned short*)(Ebase + o.x);
            unsigned int u1 = *(const unsigned short*)(Ebase + o.y);
            unsigned int u2 = *(const unsigned short*)(Ebase + o.z);
            unsigned int u3 = *(const unsigned short*)(Ebase + o.w);
            float den = bf_raw_to_f32(u0) + bf_raw_to_f32(u1) +
                        bf_raw_to_f32(u2) + bf_raw_to_f32(u3);
            acc += __fdividef(bf_raw_to_f32(un), den);
        }
    }

    // ---- block reduction -> per-block partial ----
    #pragma unroll
    for (int o = 16; o; o >>= 1) acc += __shfl_down_sync(0xFFFFFFFFu, acc, o);
    if ((tid & 31) == 0) wsum[tid >> 5] = acc;
    __syncthreads();
    if (tid < 8) {
        float v = wsum[tid];
        v += __shfl_down_sync(0xFFu, v, 4);
        v += __shfl_down_sync(0xFFu, v, 2);
        v += __shfl_down_sync(0xFFu, v, 1);
        if (tid == 0) {
            int bid = ((int)blockIdx.z * NTY + (int)blockIdx.y) * NTX + (int)blockIdx.x;
            g_partials[bid] = v;
            __threadfence();
            unsigned int t = atomicAdd(&g_count, 1u);
            s_flag = (t == NBK - 1) ? 1u : 0u;
        }
    }
    __syncthreads();

    // ---- last block: deterministic fixed-order final reduce in double ----
    if (s_flag) {
        __threadfence();
        double s = 0.0;
        for (int i = tid; i < NBK; i += 256) s += (double)g_partials[i];
        sd[tid] = s;
        __syncthreads();
        for (int st = 128; st; st >>= 1) {
            if (tid < st) sd[tid] += sd[tid + st];
            __syncthreads();
        }
        if (tid == 0) {
            out[0] = (float)sd[0];
            g_count = 0u;   // reset for next graph replay
        }
    }
}

extern "C" void kernel_launch(void* const* d_in, const int* in_sizes, int n_in,
                              void* d_out, int out_size)
{
    const float* pred = (const float*)d_in[0];
    const int*   lab  = (const int*)d_in[1];
    (void)in_sizes; (void)n_in; (void)out_size;

    dim3 grid(NTX, NTY, 4);
    steal_nms_kernel<<<grid, 256>>>(pred, lab, (float*)d_out);
}

// round 8
// speedup vs baseline: 1.0774x; 1.0774x over previous
#include <cuda_runtime.h>
#include <cuda_bf16.h>
#include <cstdint>

#define THT 16
#define TWT 32
#define PH  (THT + 4)
#define PW  (TWT + 4)
#define TPE (PH * PW)     // 720 elements per staged plane
#define HH  512
#define WW  1024
#define CC  16
#define NTY 32
#define NTX 32
#define NBK (4 * NTY * NTX)

__device__ float        g_partials[NBK];
__device__ unsigned int g_count = 0;

__host__ __device__ constexpr uint32_t pk(int a, int b, int c, int d) {
    return (uint32_t)(a & 0xFF) | ((uint32_t)(b & 0xFF) << 8) |
           ((uint32_t)(c & 0xFF) << 16) | ((uint32_t)(d & 0xFF) << 24);
}

// Negated composed-sobel weights (bytes = cols dj=-2..1 of the 5x5 kernels).
// gxx*64 = vv(row) x hh(col); gyy*64 = hh(row) x vv(col); gxy*64 = dd(row) x dd(col)
// vv=[1,4,6,4,1] hh=[1,0,-2,0,1] dd=[-1,-2,0,2,1]. Negated because vcmpeq4
// yields 0xFF (= -1 as s8) per match, so dp4a(match, -W) accumulates +W.
#define NXX0 ((int)pk(-1, 0,  2, 0))
#define NXX1 ((int)pk(-4, 0,  8, 0))
#define NXX2 ((int)pk(-6, 0, 12, 0))
#define NXXC ((int)pk(-1,-4, -6,-4))
#define NYY2 ((int)pk( 2, 8, 12, 8))
#define NXY0 ((int)pk(-1,-2,  0, 2))
#define NXY1 ((int)pk(-2,-4,  0, 4))
#define NXY3 ((int)pk( 2, 4,  0,-4))
#define NXY4 ((int)pk( 1, 2,  0,-2))

__device__ __forceinline__ float bf_raw_to_f32(unsigned int u) {
    return __uint_as_float(u << 16);
}

__global__ void __launch_bounds__(256, 6)
steal_nms_kernel(const float* __restrict__ pred, const int* __restrict__ lab,
                 float* __restrict__ out)
{
    __shared__ __nv_bfloat16               sE[CC * TPE];  // exp(pred), bf16
    __shared__ __align__(16) unsigned char sL[TPE];       // label bytes
    __shared__ int4                        sLut[3];       // tap byte-offsets per dir
    __shared__ float                       wsum[8];
    __shared__ double                      sd[256];
    __shared__ unsigned int                s_flag;

    const int tid = threadIdx.x;
    const int b  = blockIdx.z;
    const int h0 = 2 + (int)blockIdx.y * THT;
    const int w0 = 2 + (int)blockIdx.x * TWT;

    if (tid < 3) {
        int4 v;
        if (tid == 0)      v = make_int4(-4, -2, 0, 2);                          // H
        else if (tid == 1) v = make_int4(2 - 4*PW, -2*PW, -2, 2*PW - 4);         // Diag
        else               v = make_int4(-4*PW, -2*PW, 0, 2*PW);                 // V
        sLut[tid] = v;
    }

    // ---- vectorized staging: 180 float4/int4 per plane, 16B-aligned ----
    if (tid < 180) {
        int row = tid / 9;                 // 0..19
        int c4  = tid - row * 9;           // 0..8
        int gh = h0 - 2 + row; if (gh > HH - 1) gh = HH - 1;
        int gw = w0 - 2 + c4 * 4; if (gw > WW - 4) gw = WW - 4;   // clamped lanes unused by valid pixels
        const size_t goff = (size_t)gh * WW + gw;
        const int j = row * PW + c4 * 4;

        // labels: int4 -> 4 packed bytes
        int4 L = *(const int4*)(lab + (size_t)b * (HH * WW) + goff);
        uint32_t pkl = (uint32_t)(L.x & 0xFF) | ((uint32_t)(L.y & 0xFF) << 8) |
                       ((uint32_t)(L.z & 0xFF) << 16) | ((uint32_t)L.w << 24);
        *(uint32_t*)(sL + j) = pkl;

        // exp planes: LDG.128 + 4 exp + 2 bf16x2 cvt + STS.64 per class
        const float* p = pred + (size_t)b * CC * (HH * WW) + goff;
        __nv_bfloat16* se = sE + j;
        #pragma unroll 4
        for (int c = 0; c < CC; ++c) {
            float4 v = *(const float4*)p;
            __nv_bfloat162 lo = __floats2bfloat162_rn(__expf(v.x), __expf(v.y));
            __nv_bfloat162 hi = __floats2bfloat162_rn(__expf(v.z), __expf(v.w));
            uint2 st;
            st.x = *(unsigned int*)&lo;
            st.y = *(unsigned int*)&hi;
            *(uint2*)se = st;
            p  += (size_t)(HH * WW);
            se += TPE;
        }
    }
    __syncthreads();

    float acc = 0.0f;

    #pragma unroll
    for (int p2 = 0; p2 < 2; ++p2) {
        int pid = tid + p2 * 256;
        int lyy = pid >> 5, lxx = pid & 31;
        int h = h0 + lyy, w = w0 + lxx;
        if (h >= HH - 2 || w >= WW - 2) continue;   // interior only

        // ---- 5x5 label window: 5 row-words (cols -2..1), col4-word, corner
        uint32_t A0, A1, A2, A3, A4, Cw, corner;
        {
            int off0 = lyy * PW + lxx;
            uint32_t Ar[5], kb[5];
            #pragma unroll
            for (int r = 0; r < 5; ++r) {
                int off = off0 + r * PW;
                int a = off & ~3, m = off & 3;
                uint32_t u0 = *(const uint32_t*)(sL + a);
                uint32_t u1 = *(const uint32_t*)(sL + a + 4);
                Ar[r] = __byte_perm(u0, u1, 0x3210u + (uint32_t)m * 0x1111u);
                kb[r] = (u1 >> (m * 8)) & 0xFFu;
            }
            A0 = Ar[0]; A1 = Ar[1]; A2 = Ar[2]; A3 = Ar[3]; A4 = Ar[4];
            Cw = kb[0] | (kb[1] << 8) | (kb[2] << 16) | (kb[3] << 24);
            corner = kb[4];
        }

        const char* Ebase = (const char*)sE + 2 * ((lyy + 2) * PW + (lxx + 2));

        #pragma unroll 4
        for (int c = 0; c < CC; ++c, Ebase += 2 * TPE) {
            uint32_t cm = (uint32_t)c * 0x01010101u;
            int e0 = (int)__vcmpeq4(A0, cm);
            int e1 = (int)__vcmpeq4(A1, cm);
            int e2 = (int)__vcmpeq4(A2, cm);
            int e3 = (int)__vcmpeq4(A3, cm);
            int e4 = (int)__vcmpeq4(A4, cm);
            int eC = (int)__vcmpeq4(Cw, cm);
            int mk = (corner == (uint32_t)c) ? 1 : 0;   // corner weight +1 in all three kernels

            int gxx = mk, gyy = mk, gxy = mk;
            gxx = __dp4a(e0, NXX0, gxx);
            gxx = __dp4a(e1, NXX1, gxx);
            gxx = __dp4a(e2, NXX2, gxx);
            gxx = __dp4a(e3, NXX1, gxx);
            gxx = __dp4a(e4, NXX0, gxx);
            gxx = __dp4a(eC, NXXC, gxx);

            gyy = __dp4a(e0, NXXC, gyy);
            gyy = __dp4a(e2, NYY2, gyy);
            gyy = __dp4a(e4, NXXC, gyy);
            gyy = __dp4a(eC, NXX0, gyy);

            gxy = __dp4a(e0, NXY0, gxy);
            gxy = __dp4a(e1, NXY1, gxy);
            gxy = __dp4a(e3, NXY3, gxy);
            gxy = __dp4a(e4, NXY4, gxy);
            gxy = __dp4a(eC, NXY4, gxy);

            // classifier: t = s*gyy/(gxx+64eps), s = sign(-gxy+eps)
            // dir = b2 + (tp & b1);  b1 = |t|>=tan(pi/10), b2 = |t|>=tan(3pi/10)
            int ai  = (gxy <= 0) ? gyy : -gyy;
            int ua  = abs(ai);
            int ub  = abs(gxx);
            int lhs = ua << 16;
            int nz  = (ai != 0);
            int b1  = (lhs >= 21294 * ub) & nz;           // tan(pi/10)*2^16
            int b2  = (lhs >= 90203 * ub) & nz;           // tan(3pi/10)*2^16
            int tp  = ((ai ^ gxx) >= 0);                  // sign(ai)==sign(gxx)
            int dir = b2 + (tp & b1);                     // 0=H, 1=Diag, 2=V

            int4 o = sLut[dir];
            unsigned int un = *(const unsigned short*)(Ebase);
            unsigned int u0 = *(const unsigned short*)(Ebase + o.x);
            unsigned int u1 = *(const unsigned short*)(Ebase + o.y);
            unsigned int u2 = *(const unsigned short*)(Ebase + o.z);
            unsigned int u3 = *(const unsigned short*)(Ebase + o.w);
            float den = bf_raw_to_f32(u0) + bf_raw_to_f32(u1) +
                        bf_raw_to_f32(u2) + bf_raw_to_f32(u3);
            acc += __fdividef(bf_raw_to_f32(un), den);
        }
    }

    // ---- block reduction -> per-block partial ----
    #pragma unroll
    for (int o = 16; o; o >>= 1) acc += __shfl_down_sync(0xFFFFFFFFu, acc, o);
    if ((tid & 31) == 0) wsum[tid >> 5] = acc;
    __syncthreads();
    if (tid < 8) {
        float v = wsum[tid];
        v += __shfl_down_sync(0xFFu, v, 4);
        v += __shfl_down_sync(0xFFu, v, 2);
        v += __shfl_down_sync(0xFFu, v, 1);
        if (tid == 0) {
            int bid = ((int)blockIdx.z * NTY + (int)blockIdx.y) * NTX + (int)blockIdx.x;
            g_partials[bid] = v;
            __threadfence();
            unsigned int t = atomicAdd(&g_count, 1u);
            s_flag = (t == NBK - 1) ? 1u : 0u;
        }
    }
    __syncthreads();

    // ---- last block: deterministic fixed-order final reduce in double ----
    if (s_flag) {
        __threadfence();
        double s = 0.0;
        for (int i = tid; i < NBK; i += 256) s += (double)g_partials[i];
        sd[tid] = s;
        __syncthreads();
        for (int st = 128; st; st >>= 1) {
            if (tid < st) sd[tid] += sd[tid + st];
            __syncthreads();
        }
        if (tid == 0) {
            out[0] = (float)sd[0];
            g_count = 0u;   // reset for next graph replay
        }
    }
}

extern "C" void kernel_launch(void* const* d_in, const int* in_sizes, int n_in,
                              void* d_out, int out_size)
{
    const float* pred = (const float*)d_in[0];
    const int*   lab  = (const int*)d_in[1];
    (void)in_sizes; (void)n_in; (void)out_size;

    dim3 grid(NTX, NTY, 4);
    steal_nms_kernel<<<grid, 256>>>(pred, lab, (float*)d_out);
}

// round 10
// speedup vs baseline: 1.1786x; 1.0939x over previous
#include <cuda_runtime.h>
#include <cuda_bf16.h>
#include <cstdint>

#define THT 16
#define TWT 32
#define PH  (THT + 4)
#define PW  (TWT + 4)
#define TPE (PH * PW)     // 720 elements per staged plane
#define HH  512
#define WW  1024
#define CC  16
#define NTY 32
#define NTX 32
#define NBK (4 * NTY * NTX)

__device__ float        g_partials[NBK];
__device__ unsigned int g_count = 0;

__host__ __device__ constexpr uint32_t pk(int a, int b, int c, int d) {
    return (uint32_t)(a & 0xFF) | ((uint32_t)(b & 0xFF) << 8) |
           ((uint32_t)(c & 0xFF) << 16) | ((uint32_t)(d & 0xFF) << 24);
}

// Negated composed-sobel weights (bytes = cols dj=-2..1 of the 5x5 kernels).
// gxx*64 = vv(row) x hh(col); gyy*64 = hh(row) x vv(col); gxy*64 = dd(row) x dd(col)
// vv=[1,4,6,4,1] hh=[1,0,-2,0,1] dd=[-1,-2,0,2,1].
// Match flags are 0x80 (= -128 as s8) per matching byte, so dp4a(flags, -W)
// accumulates +128*W -> all g's carry a common positive scale of 128, which
// the (ratio/sign based) classifier is invariant to.
#define NXX0 ((int)pk(-1, 0,  2, 0))
#define NXX1 ((int)pk(-4, 0,  8, 0))
#define NXX2 ((int)pk(-6, 0, 12, 0))
#define NXXC ((int)pk(-1,-4, -6,-4))
#define NYY2 ((int)pk( 2, 8, 12, 8))
#define NXY0 ((int)pk(-1,-2,  0, 2))
#define NXY1 ((int)pk(-2,-4,  0, 4))
#define NXY3 ((int)pk( 2, 4,  0,-4))
#define NXY4 ((int)pk( 1, 2,  0,-2))

__device__ __forceinline__ float bf_raw_to_f32(unsigned int u) {
    return __uint_as_float(u << 16);
}

// Exact per-byte equality flags for 4-bit payload bytes (labels 0..15):
// t = a ^ bcast(c) has bytes <= 15, so t + 0x7F per byte never carries.
// Result: 0x80 at equal bytes, 0x00 elsewhere. 3 SASS ops (LOP3,IADD3,LOP3).
__device__ __forceinline__ int eqflags4(uint32_t a, uint32_t cm) {
    uint32_t t = a ^ cm;
    return (int)(~(t + 0x7F7F7F7Fu) & 0x80808080u);
}

__global__ void __launch_bounds__(256, 6)
steal_nms_kernel(const float* __restrict__ pred, const int* __restrict__ lab,
                 float* __restrict__ out)
{
    __shared__ __nv_bfloat16               sE[CC * TPE];  // exp(pred), bf16
    __shared__ __align__(16) unsigned char sL[TPE];       // label bytes
    __shared__ int4                        sLut[3];       // tap byte-offsets per dir
    __shared__ float                       wsum[8];
    __shared__ double                      sd[256];
    __shared__ unsigned int                s_flag;

    const int tid = threadIdx.x;
    const int b  = blockIdx.z;
    const int h0 = 2 + (int)blockIdx.y * THT;
    const int w0 = 2 + (int)blockIdx.x * TWT;

    if (tid < 3) {
        int4 v;
        if (tid == 0)      v = make_int4(-4, -2, 0, 2);                          // H
        else if (tid == 1) v = make_int4(2 - 4*PW, -2*PW, -2, 2*PW - 4);         // Diag
        else               v = make_int4(-4*PW, -2*PW, 0, 2*PW);                 // V
        sLut[tid] = v;
    }

    // ---- vectorized staging: 180 float4/int4 per plane, 16B-aligned ----
    if (tid < 180) {
        int row = tid / 9;                 // 0..19
        int c4  = tid - row * 9;           // 0..8
        int gh = h0 - 2 + row; if (gh > HH - 1) gh = HH - 1;
        int gw = w0 - 2 + c4 * 4; if (gw > WW - 4) gw = WW - 4;   // clamped lanes unused by valid pixels
        const size_t goff = (size_t)gh * WW + gw;
        const int j = row * PW + c4 * 4;

        // labels: int4 -> 4 packed bytes
        int4 L = *(const int4*)(lab + (size_t)b * (HH * WW) + goff);
        uint32_t pkl = (uint32_t)(L.x & 0xFF) | ((uint32_t)(L.y & 0xFF) << 8) |
                       ((uint32_t)(L.z & 0xFF) << 16) | ((uint32_t)L.w << 24);
        *(uint32_t*)(sL + j) = pkl;

        // exp planes: LDG.128 + 4 exp + 2 bf16x2 cvt + STS.64 per class
        const float* p = pred + (size_t)b * CC * (HH * WW) + goff;
        __nv_bfloat16* se = sE + j;
        #pragma unroll 4
        for (int c = 0; c < CC; ++c) {
            float4 v = *(const float4*)p;
            __nv_bfloat162 lo = __floats2bfloat162_rn(__expf(v.x), __expf(v.y));
            __nv_bfloat162 hi = __floats2bfloat162_rn(__expf(v.z), __expf(v.w));
            uint2 st;
            st.x = *(unsigned int*)&lo;
            st.y = *(unsigned int*)&hi;
            *(uint2*)se = st;
            p  += (size_t)(HH * WW);
            se += TPE;
        }
    }
    __syncthreads();

    float acc = 0.0f;

    #pragma unroll
    for (int p2 = 0; p2 < 2; ++p2) {
        int pid = tid + p2 * 256;
        int lyy = pid >> 5, lxx = pid & 31;
        int h = h0 + lyy, w = w0 + lxx;
        if (h >= HH - 2 || w >= WW - 2) continue;   // interior only

        // ---- 5x5 label window: 5 row-words (cols -2..1), col4-word, corner
        uint32_t A0, A1, A2, A3, A4, Cw, corner;
        {
            int off0 = lyy * PW + lxx;
            uint32_t Ar[5], kb[5];
            #pragma unroll
            for (int r = 0; r < 5; ++r) {
                int off = off0 + r * PW;
                int a = off & ~3, m = off & 3;
                uint32_t u0 = *(const uint32_t*)(sL + a);
                uint32_t u1 = *(const uint32_t*)(sL + a + 4);
                Ar[r] = __byte_perm(u0, u1, 0x3210u + (uint32_t)m * 0x1111u);
                kb[r] = (u1 >> (m * 8)) & 0xFFu;
            }
            A0 = Ar[0]; A1 = Ar[1]; A2 = Ar[2]; A3 = Ar[3]; A4 = Ar[4];
            Cw = kb[0] | (kb[1] << 8) | (kb[2] << 16) | (kb[3] << 24);
            corner = kb[4];
        }

        const char* Ebase = (const char*)sE + 2 * ((lyy + 2) * PW + (lxx + 2));

        #pragma unroll 4
        for (int c = 0; c < CC; ++c, Ebase += 2 * TPE) {
            uint32_t cm = (uint32_t)c * 0x01010101u;
            int e0 = eqflags4(A0, cm);
            int e1 = eqflags4(A1, cm);
            int e2 = eqflags4(A2, cm);
            int e3 = eqflags4(A3, cm);
            int e4 = eqflags4(A4, cm);
            int eC = eqflags4(Cw, cm);
            int mk = (corner == (uint32_t)c) ? 128 : 0;   // corner weight +1, scaled by 128

            int gxx = mk, gyy = mk, gxy = mk;
            gxx = __dp4a(e0, NXX0, gxx);
            gxx = __dp4a(e1, NXX1, gxx);
            gxx = __dp4a(e2, NXX2, gxx);
            gxx = __dp4a(e3, NXX1, gxx);
            gxx = __dp4a(e4, NXX0, gxx);
            gxx = __dp4a(eC, NXXC, gxx);

            gyy = __dp4a(e0, NXXC, gyy);
            gyy = __dp4a(e2, NYY2, gyy);
            gyy = __dp4a(e4, NXXC, gyy);
            gyy = __dp4a(eC, NXX0, gyy);

            gxy = __dp4a(e0, NXY0, gxy);
            gxy = __dp4a(e1, NXY1, gxy);
            gxy = __dp4a(e3, NXY3, gxy);
            gxy = __dp4a(e4, NXY4, gxy);
            gxy = __dp4a(eC, NXY4, gxy);

            // classifier (scale-invariant): t = s*gyy/(gxx+64eps), s = sign(-gxy+eps)
            // dir = b2 + (tp & b1);  b1 = |t|>=tan(pi/10), b2 = |t|>=tan(3pi/10)
            int ai  = (gxy <= 0) ? gyy : -gyy;
            int ua  = abs(ai);
            int ub  = abs(gxx);
            int lhs = ua << 16;
            int nz  = (ai != 0);
            int b1  = (lhs >= 21294 * ub) & nz;           // tan(pi/10)*2^16
            int b2  = (lhs >= 90203 * ub) & nz;           // tan(3pi/10)*2^16
            int tp  = ((ai ^ gxx) >= 0);                  // sign(ai)==sign(gxx)
            int dir = b2 + (tp & b1);                     // 0=H, 1=Diag, 2=V

            int4 o = sLut[dir];
            unsigned int un = *(const unsigned short*)(Ebase);
            unsigned int u0 = *(const unsigned short*)(Ebase + o.x);
            unsigned int u1 = *(const unsigned short*)(Ebase + o.y);
            unsigned int u2 = *(const unsigned short*)(Ebase + o.z);
            unsigned int u3 = *(const unsigned short*)(Ebase + o.w);
            float den = bf_raw_to_f32(u0) + bf_raw_to_f32(u1) +
                        bf_raw_to_f32(u2) + bf_raw_to_f32(u3);
            acc += __fdividef(bf_raw_to_f32(un), den);
        }
    }

    // ---- block reduction -> per-block partial ----
    #pragma unroll
    for (int o = 16; o; o >>= 1) acc += __shfl_down_sync(0xFFFFFFFFu, acc, o);
    if ((tid & 31) == 0) wsum[tid >> 5] = acc;
    __syncthreads();
    if (tid < 8) {
        float v = wsum[tid];
        v += __shfl_down_sync(0xFFu, v, 4);
        v += __shfl_down_sync(0xFFu, v, 2);
        v += __shfl_down_sync(0xFFu, v, 1);
        if (tid == 0) {
            int bid = ((int)blockIdx.z * NTY + (int)blockIdx.y) * NTX + (int)blockIdx.x;
            g_partials[bid] = v;
            __threadfence();
            unsigned int t = atomicAdd(&g_count, 1u);
            s_flag = (t == NBK - 1) ? 1u : 0u;
        }
    }
    __syncthreads();

    // ---- last block: deterministic fixed-order final reduce in double ----
    if (s_flag) {
        __threadfence();
        double s = 0.0;
        for (int i = tid; i < NBK; i += 256) s += (double)g_partials[i];
        sd[tid] = s;
        __syncthreads();
        for (int st = 128; st; st >>= 1) {
            if (tid < st) sd[tid] += sd[tid + st];
            __syncthreads();
        }
        if (tid == 0) {
            out[0] = (float)sd[0];
            g_count = 0u;   // reset for next graph replay
        }
    }
}

extern "C" void kernel_launch(void* const* d_in, const int* in_sizes, int n_in,
                              void* d_out, int out_size)
{
    const float* pred = (const float*)d_in[0];
    const int*   lab  = (const int*)d_in[1];
    (void)in_sizes; (void)n_in; (void)out_size;

    dim3 grid(NTX, NTY, 4);
    steal_nms_kernel<<<grid, 256>>>(pred, lab, (float*)d_out);
}